// round 15
// baseline (speedup 1.0000x reference)
#include <cuda_runtime.h>
#include <cuda_bf16.h>
#include <stdint.h>
#include <math.h>

#define Bz 256
#define Sz 128
#define Hz 14
#define Wz 14
#define Tz 12
#define Dz 512
#define HWz (Hz*Wz)
#define Mbig (Bz*HWz)   // 50176

// ---------------- scratch (device globals; no allocation) ----------------
__device__ float g_qi[Bz*Dz];
__device__ float g_cqi[Bz*Dz];
__device__ float g_cai[Bz*Sz];
__device__ float g_ci[Bz*Dz];
__device__ float g_rm[Bz*Dz];
__device__ float g_ri[Bz*Dz];
__device__ float g_mi_info[Bz*Dz];
__device__ float g_mi_sa[Bz*Dz];
__device__ float g_mi_prime[Bz*Dz];
__device__ float g_rai[(size_t)Mbig*Dz];
__device__ __nv_bfloat16 g_K_bf[(size_t)Mbig*Dz];
__device__ __nv_bfloat16 g_rk_bf[(size_t)Mbig*Dz];   // rm ⊙ (K@W_rk + b_rk)
__device__ __nv_bfloat16 g_ip_bf[(size_t)Mbig*Dz];   // ci ⊙ (concat@W_rik + b_rik)
__device__ __nv_bfloat16 g_Wt_rk[Dz*Dz];
__device__ __nv_bfloat16 g_Wt_rik[2*Dz*Dz];
__device__ __nv_bfloat16 g_Wt_rci[Dz*Dz];

// ================= helpers =================
__device__ __forceinline__ uint32_t smem_u32(const void* p) {
    uint32_t a;
    asm("{ .reg .u64 t; cvta.to.shared.u64 t, %1; cvt.u32.u64 %0, t; }" : "=r"(a) : "l"(p));
    return a;
}
__device__ __forceinline__ void cp16(uint32_t dst, const void* src) {
    asm volatile("cp.async.cg.shared.global [%0], [%1], 16;" :: "r"(dst), "l"(src) : "memory");
}
__device__ __forceinline__ void mma_bf16(float* c, uint32_t a0, uint32_t a1,
                                         uint32_t a2, uint32_t a3,
                                         uint32_t b0, uint32_t b1) {
    asm volatile("mma.sync.aligned.m16n8k16.row.col.f32.bf16.bf16.f32 "
        "{%0,%1,%2,%3}, {%4,%5,%6,%7}, {%8,%9}, {%0,%1,%2,%3};"
        : "+f"(c[0]), "+f"(c[1]), "+f"(c[2]), "+f"(c[3])
        : "r"(a0), "r"(a1), "r"(a2), "r"(a3), "r"(b0), "r"(b1));
}
__device__ __forceinline__ void ldm4(uint32_t& r0, uint32_t& r1, uint32_t& r2,
                                     uint32_t& r3, uint32_t addr) {
    asm volatile("ldmatrix.sync.aligned.m8n8.x4.shared.b16 {%0,%1,%2,%3}, [%4];"
        : "=r"(r0), "=r"(r1), "=r"(r2), "=r"(r3) : "r"(addr));
}

// fast exp on the FMA pipe (keeps MUFU free)
__device__ __forceinline__ float fexp(float x) {
    float t = fmaxf(x * 1.44269504f, -126.0f);
    float n = floorf(t);
    float f = t - n;
    float p = 1.8775767e-3f;
    p = fmaf(p, f, 8.9893397e-3f);
    p = fmaf(p, f, 5.5826318e-2f);
    p = fmaf(p, f, 2.4015361e-1f);
    p = fmaf(p, f, 6.9315308e-1f);
    p = fmaf(p, f, 9.9999994e-1f);
    return __int_as_float(((int)n + 127) << 23) * p;
}

#define TSTRIDE 144                 // bytes per smem tile row (64 bf16 + 8 pad)
#define TILE_BYTES (128*TSTRIDE)    // 18432
#define HG_SMEM (6*TILE_BYTES)      // 110592: A x3 stages, B x3 stages
#define FMA_N0 384                  // FFMA path handles cols [384, 512)

// ================= hybrid GEMM: HMMA (cols 0..383) + FFMA (cols 384..511) =========
// C[M,512] = Acat[M,Ktot] @ W[Ktot,512] + bias, then optional ⊙ scale[row/196, col]
// Acat[m,k] = (k<K1) ? A1[m,k] : A2[m,k-K1]   (A2 row stride 512, bf16)
// Bt = W^T bf16 [512][Ktot] (HMMA); Bf = W fp32 [Ktot][512] (FFMA).
// grid = (4, M/128): x<3 -> HMMA tile n0=x*128; x==3 -> FFMA tile cols 384..511.
__global__ void __launch_bounds__(256, 2) hybrid_gemm_kernel(
    const __nv_bfloat16* __restrict__ A1,
    const __nv_bfloat16* __restrict__ A2,
    const __nv_bfloat16* __restrict__ Bt,
    const float* __restrict__ Bf,
    const float* __restrict__ bias,
    const float* __restrict__ scale,
    void* __restrict__ Cout, int c_is_bf16,
    int K1, int Ktot)
{
    extern __shared__ char sm[];
    const int tid = threadIdx.x;
    const int m0  = blockIdx.y * 128;

    if (blockIdx.x < 3) {
        // ======================= HMMA path (tensor pipe) =======================
        const uint32_t sa_base = smem_u32(sm);
        const uint32_t sb_base = sa_base + 3 * TILE_BYTES;
        const int n0   = blockIdx.x * 128;
        const int warp = tid >> 5;
        const int lane = tid & 31;
        const int wm = warp >> 2;
        const int wn = warp & 3;
        const int g  = lane >> 2;
        const int t  = lane & 3;

        float acc[4][4][4];
        #pragma unroll
        for (int i = 0; i < 4; i++)
            #pragma unroll
            for (int j = 0; j < 4; j++)
                #pragma unroll
                for (int k = 0; k < 4; k++) acc[i][j][k] = 0.f;

        const int nch = Ktot >> 6;

        auto load_tile = [&](int c) {
            const int kt = c << 6;
            const int s = c % 3;
            uint32_t ab = sa_base + s * TILE_BYTES;
            uint32_t bb = sb_base + s * TILE_BYTES;
            #pragma unroll
            for (int i = 0; i < 4; i++) {
                int chunk = tid + (i << 8);
                int row = chunk >> 3, cc = chunk & 7;
                int kg = kt + (cc << 3);
                const __nv_bfloat16* sa = (kg < K1)
                    ? (A1 + (size_t)(m0 + row) * K1 + kg)
                    : (A2 + (size_t)(m0 + row) * Dz + (kg - K1));
                cp16(ab + row * TSTRIDE + cc * 16, sa);
                cp16(bb + row * TSTRIDE + cc * 16,
                     Bt + (size_t)(n0 + row) * Ktot + kt + (cc << 3));
            }
            asm volatile("cp.async.commit_group;" ::: "memory");
        };

        load_tile(0);
        load_tile(1);
        for (int c = 0; c < nch; c++) {
            if (c + 1 < nch) asm volatile("cp.async.wait_group 1;" ::: "memory");
            else             asm volatile("cp.async.wait_group 0;" ::: "memory");
            __syncthreads();
            if (c + 2 < nch) load_tile(c + 2);

            const int s = c % 3;
            const uint32_t ab = sa_base + s * TILE_BYTES;
            const uint32_t bb = sb_base + s * TILE_BYTES;
            #pragma unroll
            for (int ks = 0; ks < 4; ks++) {
                uint32_t bfr[4][2];
                #pragma unroll
                for (int j = 0; j < 2; j++) {
                    uint32_t addr = bb + (uint32_t)((wn * 32 + j * 16 + ((lane >> 4) & 1) * 8
                                    + (lane & 7)) * TSTRIDE + ks * 32 + ((lane >> 3) & 1) * 16);
                    ldm4(bfr[2*j][0], bfr[2*j][1], bfr[2*j+1][0], bfr[2*j+1][1], addr);
                }
                #pragma unroll
                for (int am = 0; am < 4; am++) {
                    uint32_t addr = ab + (uint32_t)((wm * 64 + am * 16 + (lane & 15)) * TSTRIDE
                                    + ks * 32 + ((lane >> 4) & 1) * 16);
                    uint32_t a0, a1, a2, a3;
                    ldm4(a0, a1, a2, a3, addr);
                    #pragma unroll
                    for (int an = 0; an < 4; an++)
                        mma_bf16(acc[am][an], a0, a1, a2, a3, bfr[an][0], bfr[an][1]);
                }
            }
        }

        #pragma unroll
        for (int am = 0; am < 4; am++) {
            int r0 = m0 + wm * 64 + am * 16 + g;
            int r1 = r0 + 8;
            #pragma unroll
            for (int an = 0; an < 4; an++) {
                int col = n0 + wn * 32 + an * 8 + t * 2;
                float b0 = bias[col], b1 = bias[col + 1];
                float v00 = acc[am][an][0] + b0, v01 = acc[am][an][1] + b1;
                float v10 = acc[am][an][2] + b0, v11 = acc[am][an][3] + b1;
                if (scale) {
                    const float* s0 = scale + (size_t)(r0 / HWz) * Dz + col;
                    const float* s1 = scale + (size_t)(r1 / HWz) * Dz + col;
                    v00 *= s0[0]; v01 *= s0[1];
                    v10 *= s1[0]; v11 *= s1[1];
                }
                if (c_is_bf16) {
                    union { __nv_bfloat162 h; uint32_t u; } p0, p1;
                    p0.h = __floats2bfloat162_rn(v00, v01);
                    p1.h = __floats2bfloat162_rn(v10, v11);
                    *(uint32_t*)((__nv_bfloat16*)Cout + (size_t)r0 * Dz + col) = p0.u;
                    *(uint32_t*)((__nv_bfloat16*)Cout + (size_t)r1 * Dz + col) = p1.u;
                } else {
                    *(float2*)((float*)Cout + (size_t)r0 * Dz + col) = make_float2(v00, v01);
                    *(float2*)((float*)Cout + (size_t)r1 * Dz + col) = make_float2(v10, v11);
                }
            }
        }
    } else {
        // ======================= FFMA path (fma pipe), cols 384..511 ============
        float* As = (float*)sm;            // [8][128]
        float* Bs = (float*)(sm + 4096);   // [8][128]
        const int tx = tid & 15;
        const int ty = tid >> 4;
        const int aRow = tid >> 1;
        const int aCol = (tid & 1) << 2;
        const int bRow = tid >> 5;
        const int bCol = (tid & 31) << 2;

        float acc[8][8];
        #pragma unroll
        for (int i = 0; i < 8; i++)
            #pragma unroll
            for (int j = 0; j < 8; j++) acc[i][j] = 0.f;

        for (int kt = 0; kt < Ktot; kt += 8) {
            int kg = kt + aCol;
            const __nv_bfloat16* ap = (kg < K1)
                ? (A1 + (size_t)(m0 + aRow) * K1 + kg)
                : (A2 + (size_t)(m0 + aRow) * Dz + (kg - K1));
            uint2 araw = *(const uint2*)ap;          // 4 bf16
            float2 f01 = __bfloat1622float2(((const __nv_bfloat162*)&araw)[0]);
            float2 f23 = __bfloat1622float2(((const __nv_bfloat162*)&araw)[1]);
            As[(aCol + 0) * 128 + aRow] = f01.x;
            As[(aCol + 1) * 128 + aRow] = f01.y;
            As[(aCol + 2) * 128 + aRow] = f23.x;
            As[(aCol + 3) * 128 + aRow] = f23.y;
            *(float4*)&Bs[bRow * 128 + bCol] =
                *(const float4*)(Bf + (size_t)(kt + bRow) * Dz + FMA_N0 + bCol);
            __syncthreads();
            #pragma unroll
            for (int k = 0; k < 8; k++) {
                float ar[8], br[8];
                #pragma unroll
                for (int i = 0; i < 8; i++) ar[i] = As[k * 128 + ty * 8 + i];
                #pragma unroll
                for (int j = 0; j < 8; j++) br[j] = Bs[k * 128 + tx * 8 + j];
                #pragma unroll
                for (int i = 0; i < 8; i++)
                    #pragma unroll
                    for (int j = 0; j < 8; j++)
                        acc[i][j] = fmaf(ar[i], br[j], acc[i][j]);
            }
            __syncthreads();
        }

        #pragma unroll
        for (int i = 0; i < 8; i++) {
            int row = m0 + ty * 8 + i;
            int colb = FMA_N0 + tx * 8;
            float v[8];
            #pragma unroll
            for (int j = 0; j < 8; j++) {
                v[j] = acc[i][j] + bias[colb + j];
            }
            if (scale) {
                const float* sp = scale + (size_t)(row / HWz) * Dz + colb;
                #pragma unroll
                for (int j = 0; j < 8; j++) v[j] *= sp[j];
            }
            if (c_is_bf16) {
                union { __nv_bfloat162 h; uint32_t u; } p0, p1, p2, p3;
                p0.h = __floats2bfloat162_rn(v[0], v[1]);
                p1.h = __floats2bfloat162_rn(v[2], v[3]);
                p2.h = __floats2bfloat162_rn(v[4], v[5]);
                p3.h = __floats2bfloat162_rn(v[6], v[7]);
                *(uint4*)((__nv_bfloat16*)Cout + (size_t)row * Dz + colb) =
                    make_uint4(p0.u, p1.u, p2.u, p3.u);
            } else {
                float* cp = (float*)Cout + (size_t)row * Dz + colb;
                *(float4*)cp = make_float4(v[0], v[1], v[2], v[3]);
                *(float4*)(cp + 4) = make_float4(v[4], v[5], v[6], v[7]);
            }
        }
    }
}

// ---------------- fp32 -> bf16 bulk convert ----------------
__global__ void __launch_bounds__(256) f2bf_kernel(const float* __restrict__ in,
                                                   __nv_bfloat16* __restrict__ out)
{
    size_t i = ((size_t)blockIdx.x * 256 + threadIdx.x) * 4;
    float4 v = *(const float4*)(in + i);
    union { __nv_bfloat162 h; uint32_t u; } p0, p1;
    p0.h = __floats2bfloat162_rn(v.x, v.y);
    p1.h = __floats2bfloat162_rn(v.z, v.w);
    *(uint2*)(out + i) = make_uint2(p0.u, p1.u);
}

// ---------------- weight transpose: Wt[n][k] = (bf16) W[k][n] ----------------
__global__ void __launch_bounds__(256) transpose_w_kernel(
    const float* __restrict__ W, __nv_bfloat16* __restrict__ Wt, int K, int N)
{
    __shared__ float t[32][33];
    int k0 = blockIdx.x * 32, n0 = blockIdx.y * 32;
    int x = threadIdx.x & 31, y = threadIdx.x >> 5;
    #pragma unroll
    for (int j = 0; j < 32; j += 8)
        t[y + j][x] = W[(size_t)(k0 + y + j) * N + n0 + x];
    __syncthreads();
    #pragma unroll
    for (int j = 0; j < 32; j += 8)
        Wt[(size_t)(n0 + y + j) * K + k0 + x] = __float2bfloat16(t[x][y + j]);
}

// ---------------- fp32 SGEMM with concat-A and stacked-B support ----------------
__global__ void __launch_bounds__(256) sgemm_kernel(
    const float* __restrict__ A1, const float* __restrict__ A2,
    const float* __restrict__ B1, const float* __restrict__ B2,
    const float* __restrict__ bias, const float* __restrict__ bias2,
    float* __restrict__ C,
    int M, int N, int K1, int KB1, int Ktot)
{
    __shared__ float As[8][128];
    __shared__ float Bs[8][128];
    const int tid = threadIdx.x;
    const int m0 = blockIdx.y * 128;
    const int n0 = blockIdx.x * 128;
    const int tx = tid & 15;
    const int ty = tid >> 4;
    const int aRow = tid >> 1;
    const int aCol = (tid & 1) << 2;
    const int bRow = tid >> 5;
    const int bCol = (tid & 31) << 2;

    float acc[8][8];
    #pragma unroll
    for (int i = 0; i < 8; i++)
        #pragma unroll
        for (int j = 0; j < 8; j++) acc[i][j] = 0.f;

    for (int kt = 0; kt < Ktot; kt += 8) {
        int kg = kt + aCol;
        const float* ap = (kg < K1)
            ? (A1 + (size_t)(m0 + aRow) * K1 + kg)
            : (A2 + (size_t)(m0 + aRow) * Dz + (kg - K1));
        float4 a = *(const float4*)ap;
        As[aCol + 0][aRow] = a.x;
        As[aCol + 1][aRow] = a.y;
        As[aCol + 2][aRow] = a.z;
        As[aCol + 3][aRow] = a.w;
        int kr = kt + bRow;
        const float* bp = (kr < KB1)
            ? (B1 + (size_t)kr * N + n0 + bCol)
            : (B2 + (size_t)(kr - KB1) * N + n0 + bCol);
        *(float4*)&Bs[bRow][bCol] = *(const float4*)bp;
        __syncthreads();
        #pragma unroll
        for (int k = 0; k < 8; k++) {
            float ar[8], br[8];
            #pragma unroll
            for (int i = 0; i < 8; i++) ar[i] = As[k][ty * 8 + i];
            #pragma unroll
            for (int j = 0; j < 8; j++) br[j] = Bs[k][tx * 8 + j];
            #pragma unroll
            for (int i = 0; i < 8; i++)
                #pragma unroll
                for (int j = 0; j < 8; j++)
                    acc[i][j] = fmaf(ar[i], br[j], acc[i][j]);
        }
        __syncthreads();
    }
    #pragma unroll
    for (int i = 0; i < 8; i++) {
        int row = m0 + ty * 8 + i;
        float* crow = C + (size_t)row * N + n0 + tx * 8;
        #pragma unroll
        for (int j = 0; j < 8; j++) {
            float v = acc[i][j] + bias[n0 + tx * 8 + j];
            if (bias2) v += bias2[n0 + tx * 8 + j];
            crow[j] = v;
        }
    }
}

// ---------------- cai[b,s] = sum_d cqi[b,d]*cws[b,s,d]*W_cai[d] ----------------
__global__ void __launch_bounds__(256) cai_kernel(const float* __restrict__ cws,
                                                  const float* __restrict__ Wcai)
{
    int warp = (blockIdx.x * blockDim.x + threadIdx.x) >> 5;
    int lane = threadIdx.x & 31;
    if (warp >= Bz * Sz) return;
    int b = warp / Sz;
    const float* cq = g_cqi + b * Dz;
    const float* cw = cws + (size_t)warp * Dz;
    float sum = 0.f;
    #pragma unroll 4
    for (int d = lane; d < Dz; d += 32)
        sum += cq[d] * cw[d] * Wcai[d];
    #pragma unroll
    for (int o = 16; o; o >>= 1) sum += __shfl_xor_sync(0xffffffffu, sum, o);
    if (lane == 0) g_cai[warp] = sum;
}

// ---------------- softmax over S + ci reduction ----------------
__global__ void __launch_bounds__(128) ci_kernel(const float* __restrict__ cws)
{
    int b = blockIdx.x, tid = threadIdx.x;
    __shared__ float wsm[Sz];
    __shared__ float red[4];
    float x = g_cai[b * Sz + tid];
    float m = x;
    #pragma unroll
    for (int o = 16; o; o >>= 1) m = fmaxf(m, __shfl_xor_sync(0xffffffffu, m, o));
    if ((tid & 31) == 0) red[tid >> 5] = m;
    __syncthreads();
    float bm = fmaxf(fmaxf(red[0], red[1]), fmaxf(red[2], red[3]));
    __syncthreads();
    float e = expf(x - bm);
    float s = e;
    #pragma unroll
    for (int o = 16; o; o >>= 1) s += __shfl_xor_sync(0xffffffffu, s, o);
    if ((tid & 31) == 0) red[tid >> 5] = s;
    __syncthreads();
    float bs = red[0] + red[1] + red[2] + red[3];
    wsm[tid] = e / bs;
    __syncthreads();
    for (int d = tid; d < Dz; d += 128) {
        float acc = 0.f;
        #pragma unroll 8
        for (int s2 = 0; s2 < Sz; s2++)
            acc += wsm[s2] * cws[((size_t)b * Sz + s2) * Dz + d];
        g_ci[b * Dz + d] = acc;
    }
}

// ---------------- double softmax + ri, smem-staged, FMA-pipe exp ----------------
#define RS_SMEM (HWz*128*4)   // 196*128 fp32 = 100352 B
__global__ void __launch_bounds__(128) rsoft_kernel(const float* __restrict__ rai,
                                                    const float* __restrict__ Kt)
{
    extern __shared__ float sd[];   // [196][128]
    const int b = blockIdx.x;
    const int d0 = blockIdx.y * 128;
    const int tid = threadIdx.x;
    const float* src = rai + (size_t)b * HWz * Dz + d0;

    for (int i = tid; i < HWz * 32; i += 128) {
        int pos = i >> 5, c4 = (i & 31) << 2;
        *(float4*)(sd + pos * 128 + c4) = *(const float4*)(src + (size_t)pos * Dz + c4);
    }
    __syncthreads();

    for (int w = 0; w < Wz; w++) {
        float v[Hz];
        float mx = -1e30f;
        #pragma unroll
        for (int h = 0; h < Hz; h++) { v[h] = sd[(h * Wz + w) * 128 + tid]; mx = fmaxf(mx, v[h]); }
        float s = 0.f;
        #pragma unroll
        for (int h = 0; h < Hz; h++) { v[h] = fexp(v[h] - mx); s += v[h]; }
        float inv = 1.f / s;
        #pragma unroll
        for (int h = 0; h < Hz; h++) sd[(h * Wz + w) * 128 + tid] = v[h] * inv;
    }
    __syncthreads();

    const float* kp = Kt + (size_t)b * HWz * Dz + d0 + tid;
    float acc = 0.f;
    for (int h = 0; h < Hz; h++) {
        float v[Wz];
        float mx = -1e30f;
        #pragma unroll
        for (int w = 0; w < Wz; w++) { v[w] = sd[(h * Wz + w) * 128 + tid]; mx = fmaxf(mx, v[w]); }
        float s = 0.f;
        #pragma unroll
        for (int w = 0; w < Wz; w++) { v[w] = fexp(v[w] - mx); s += v[w]; }
        float inv = 1.f / s;
        #pragma unroll
        for (int w = 0; w < Wz; w++) acc += v[w] * inv * kp[(size_t)(h * Wz + w) * Dz];
    }
    g_ri[b * Dz + d0 + tid] = acc;
}

// ---------------- write attention ----------------
__global__ void __launch_bounds__(512) sa_kernel(const float* __restrict__ C_past,
                                                 const float* __restrict__ M_past,
                                                 const float* __restrict__ Wwcc)
{
    int b = blockIdx.x, tid = threadIdx.x;
    int lane = tid & 31, warp = tid >> 5;
    __shared__ float z[16];
    __shared__ float wsm[Tz];
    if (warp < Tz) {
        const float* cp = C_past + ((size_t)b * Tz + warp) * Dz;
        const float* cb = g_ci + b * Dz;
        float sum = 0.f;
        #pragma unroll 4
        for (int d = lane; d < Dz; d += 32) sum += cb[d] * cp[d] * Wwcc[d];
        #pragma unroll
        for (int o = 16; o; o >>= 1) sum += __shfl_xor_sync(0xffffffffu, sum, o);
        if (lane == 0) z[warp] = sum;
    }
    __syncthreads();
    if (tid == 0) {
        float mx = -1e30f;
        for (int t = 0; t < Tz; t++) mx = fmaxf(mx, z[t]);
        float s = 0.f;
        for (int t = 0; t < Tz; t++) { float e = expf(z[t] - mx); wsm[t] = e; s += e; }
        float inv = 1.f / s;
        for (int t = 0; t < Tz; t++) wsm[t] *= inv;
    }
    __syncthreads();
    float acc = 0.f;
    #pragma unroll
    for (int t = 0; t < Tz; t++)
        acc += wsm[t] * M_past[((size_t)b * Tz + t) * Dz + tid];
    g_mi_sa[b * Dz + tid] = acc;
}

// ---------------- gate + final ----------------
__global__ void __launch_bounds__(512) final_kernel(const float* __restrict__ mi_1,
                                                    const float* __restrict__ Wwci,
                                                    const float* __restrict__ bwci,
                                                    float* __restrict__ out)
{
    int b = blockIdx.x, tid = threadIdx.x;
    __shared__ float red[16];
    __shared__ float gsh;
    float civ = g_ci[b * Dz + tid];
    float sum = civ * Wwci[tid];
    #pragma unroll
    for (int o = 16; o; o >>= 1) sum += __shfl_xor_sync(0xffffffffu, sum, o);
    if ((tid & 31) == 0) red[tid >> 5] = sum;
    __syncthreads();
    if (tid < 32) {
        float v = (tid < 16) ? red[tid] : 0.f;
        #pragma unroll
        for (int o = 8; o; o >>= 1) v += __shfl_xor_sync(0xffffffffu, v, o);
        if (tid == 0) gsh = 1.f / (1.f + expf(-(v + bwci[0])));
    }
    __syncthreads();
    float g = gsh;
    float mi = g * mi_1[b * Dz + tid] + (1.f - g) * g_mi_prime[b * Dz + tid];
    out[b * Dz + tid] = civ;
    out[(size_t)Bz * Dz + b * Dz + tid] = mi;
}

// ---------------- launch ----------------
extern "C" void kernel_launch(void* const* d_in, const int* in_sizes, int n_in,
                              void* d_out, int out_size)
{
    const float* ci_1   = (const float*)d_in[0];
    const float* mi_1   = (const float*)d_in[1];
    const float* q      = (const float*)d_in[2];
    const float* cws    = (const float*)d_in[3];
    const float* Kt     = (const float*)d_in[4];
    const float* C_past = (const float*)d_in[5];
    const float* M_past = (const float*)d_in[6];
    const float* W_cq   = (const float*)d_in[7];
    const float* b_cq   = (const float*)d_in[8];
    const float* W_cqi  = (const float*)d_in[9];
    const float* b_cqi  = (const float*)d_in[10];
    const float* W_cai  = (const float*)d_in[11];
    const float* W_rm   = (const float*)d_in[13];
    const float* b_rm   = (const float*)d_in[14];
    const float* W_rk   = (const float*)d_in[15];
    const float* b_rk   = (const float*)d_in[16];
    const float* W_rik  = (const float*)d_in[17];
    const float* b_rik  = (const float*)d_in[18];
    const float* W_rci  = (const float*)d_in[19];
    const float* b_rci  = (const float*)d_in[20];
    const float* W_wrm  = (const float*)d_in[21];
    const float* b_wrm  = (const float*)d_in[22];
    const float* W_wcc  = (const float*)d_in[23];
    const float* W_wsa  = (const float*)d_in[25];
    const float* b_wsa  = (const float*)d_in[26];
    const float* W_winfo= (const float*)d_in[27];
    const float* b_winfo= (const float*)d_in[28];
    const float* W_wci  = (const float*)d_in[29];
    const float* b_wci  = (const float*)d_in[30];
    float* out = (float*)d_out;

    float *qi, *cqi, *ci, *rm, *rai, *ri, *mi_info, *mi_sa, *mi_prime;
    __nv_bfloat16 *K_bf, *rk_bf, *ip_bf, *Wt_rk, *Wt_rik, *Wt_rci;
    cudaGetSymbolAddress((void**)&qi, g_qi);
    cudaGetSymbolAddress((void**)&cqi, g_cqi);
    cudaGetSymbolAddress((void**)&ci, g_ci);
    cudaGetSymbolAddress((void**)&rm, g_rm);
    cudaGetSymbolAddress((void**)&rai, g_rai);
    cudaGetSymbolAddress((void**)&ri, g_ri);
    cudaGetSymbolAddress((void**)&mi_info, g_mi_info);
    cudaGetSymbolAddress((void**)&mi_sa, g_mi_sa);
    cudaGetSymbolAddress((void**)&mi_prime, g_mi_prime);
    cudaGetSymbolAddress((void**)&K_bf, g_K_bf);
    cudaGetSymbolAddress((void**)&rk_bf, g_rk_bf);
    cudaGetSymbolAddress((void**)&ip_bf, g_ip_bf);
    cudaGetSymbolAddress((void**)&Wt_rk, g_Wt_rk);
    cudaGetSymbolAddress((void**)&Wt_rik, g_Wt_rik);
    cudaGetSymbolAddress((void**)&Wt_rci, g_Wt_rci);

    cudaFuncSetAttribute(hybrid_gemm_kernel,
                         cudaFuncAttributeMaxDynamicSharedMemorySize, HG_SMEM);
    cudaFuncSetAttribute(rsoft_kernel,
                         cudaFuncAttributeMaxDynamicSharedMemorySize, RS_SMEM);

    dim3 gs(Dz / 128, Bz / 128);     // small GEMMs: (4, 2)
    dim3 gh(4, Mbig / 128);          // hybrid GEMMs: x<3 HMMA, x==3 FFMA

    // ---- precompute ----
    f2bf_kernel<<<(Mbig * Dz) / 1024, 256>>>(Kt, K_bf);
    transpose_w_kernel<<<dim3(Dz/32, Dz/32), 256>>>(W_rk, Wt_rk, Dz, Dz);
    transpose_w_kernel<<<dim3(2*Dz/32, Dz/32), 256>>>(W_rik, Wt_rik, 2*Dz, Dz);
    transpose_w_kernel<<<dim3(Dz/32, Dz/32), 256>>>(W_rci, Wt_rci, Dz, Dz);
    sgemm_kernel<<<gs, 256>>>(mi_1, nullptr, W_rm, nullptr, b_rm, nullptr, rm,
                              Bz, Dz, Dz, 2*Dz, Dz);

    // ---- GEMM1: rk_bf = rm ⊙ (K @ W_rk + b_rk) ----
    hybrid_gemm_kernel<<<gh, 256, HG_SMEM>>>(K_bf, nullptr, Wt_rk, W_rk,
                                             b_rk, rm, rk_bf, 1, Dz, Dz);

    // ---- control (fp32) ----
    sgemm_kernel<<<gs, 256>>>(q, nullptr, W_cq, nullptr, b_cq, nullptr, qi,
                              Bz, Dz, Dz, 2*Dz, Dz);
    sgemm_kernel<<<gs, 256>>>(ci_1, qi, W_cqi, nullptr, b_cqi, nullptr, cqi,
                              Bz, Dz, Dz, 2*Dz, 2*Dz);
    cai_kernel<<<(Bz * Sz) / 8, 256>>>(cws, W_cai);
    ci_kernel<<<Bz, 128>>>(cws);

    // ---- read path ----
    // ip_bf = ci ⊙ (concat(rk_bf, K) @ W_rik + b_rik)
    hybrid_gemm_kernel<<<gh, 256, HG_SMEM>>>(rk_bf, K_bf, Wt_rik, W_rik,
                                             b_rik, ci, ip_bf, 1, Dz, 2*Dz);
    // rai = ip_bf @ W_rci + b_rci  (fp32 out)
    hybrid_gemm_kernel<<<gh, 256, HG_SMEM>>>(ip_bf, nullptr, Wt_rci, W_rci,
                                             b_rci, nullptr, rai, 0, Dz, Dz);
    rsoft_kernel<<<dim3(Bz, Dz/128), 128, RS_SMEM>>>(rai, Kt);

    // ---- write (fp32) ----
    sgemm_kernel<<<gs, 256>>>(ri, mi_1, W_wrm, nullptr, b_wrm, nullptr, mi_info,
                              Bz, Dz, Dz, 2*Dz, 2*Dz);
    sa_kernel<<<Bz, 512>>>(C_past, M_past, W_wcc);
    sgemm_kernel<<<gs, 256>>>(mi_sa, mi_info, W_wsa, W_winfo, b_wsa, b_winfo, mi_prime,
                              Bz, Dz, Dz, Dz, 2*Dz);
    final_kernel<<<Bz, 512>>>(mi_1, W_wci, b_wci, out);
}

// round 16
// speedup vs baseline: 2.3970x; 2.3970x over previous
#include <cuda_runtime.h>
#include <cuda_bf16.h>
#include <stdint.h>
#include <math.h>

#define Bz 256
#define Sz 128
#define Hz 14
#define Wz 14
#define Tz 12
#define Dz 512
#define HWz (Hz*Wz)
#define Mbig (Bz*HWz)   // 50176

// ---------------- scratch (device globals; no allocation) ----------------
__device__ float g_qi[Bz*Dz];
__device__ float g_cqi[Bz*Dz];
__device__ float g_cai[Bz*Sz];
__device__ float g_ci[Bz*Dz];
__device__ float g_rm[Bz*Dz];
__device__ float g_ri[Bz*Dz];
__device__ float g_mi_info[Bz*Dz];
__device__ float g_mi_sa[Bz*Dz];
__device__ float g_mi_prime[Bz*Dz];
__device__ __nv_bfloat16 g_rai_bf[(size_t)Mbig*Dz];
__device__ __nv_bfloat16 g_K_bf[(size_t)Mbig*Dz];
__device__ __nv_bfloat16 g_rk_bf[(size_t)Mbig*Dz];   // rm ⊙ (K@W_rk + b_rk)
__device__ __nv_bfloat16 g_ip_bf[(size_t)Mbig*Dz];   // ci ⊙ (concat@W_rik + b_rik)
__device__ __nv_bfloat16 g_Wt_rk[Dz*Dz];
__device__ __nv_bfloat16 g_Wt_rik[2*Dz*Dz];
__device__ __nv_bfloat16 g_Wt_rci[Dz*Dz];

// ================= helpers =================
__device__ __forceinline__ uint32_t smem_u32(const void* p) {
    uint32_t a;
    asm("{ .reg .u64 t; cvta.to.shared.u64 t, %1; cvt.u32.u64 %0, t; }" : "=r"(a) : "l"(p));
    return a;
}
__device__ __forceinline__ void cp16(uint32_t dst, const void* src) {
    asm volatile("cp.async.cg.shared.global [%0], [%1], 16;" :: "r"(dst), "l"(src) : "memory");
}
__device__ __forceinline__ void mma_bf16(float* c, uint32_t a0, uint32_t a1,
                                         uint32_t a2, uint32_t a3,
                                         uint32_t b0, uint32_t b1) {
    asm volatile("mma.sync.aligned.m16n8k16.row.col.f32.bf16.bf16.f32 "
        "{%0,%1,%2,%3}, {%4,%5,%6,%7}, {%8,%9}, {%0,%1,%2,%3};"
        : "+f"(c[0]), "+f"(c[1]), "+f"(c[2]), "+f"(c[3])
        : "r"(a0), "r"(a1), "r"(a2), "r"(a3), "r"(b0), "r"(b1));
}
__device__ __forceinline__ void ldm4(uint32_t& r0, uint32_t& r1, uint32_t& r2,
                                     uint32_t& r3, uint32_t addr) {
    asm volatile("ldmatrix.sync.aligned.m8n8.x4.shared.b16 {%0,%1,%2,%3}, [%4];"
        : "=r"(r0), "=r"(r1), "=r"(r2), "=r"(r3) : "r"(addr));
}

// fast exp on the FMA pipe
__device__ __forceinline__ float fexp(float x) {
    float t = fmaxf(x * 1.44269504f, -126.0f);
    float n = floorf(t);
    float f = t - n;
    float p = 1.8775767e-3f;
    p = fmaf(p, f, 8.9893397e-3f);
    p = fmaf(p, f, 5.5826318e-2f);
    p = fmaf(p, f, 2.4015361e-1f);
    p = fmaf(p, f, 6.9315308e-1f);
    p = fmaf(p, f, 9.9999994e-1f);
    return __int_as_float(((int)n + 127) << 23) * p;
}

#define TSTRIDE 144                 // bytes per smem tile row (64 bf16 + 8 pad)
#define TILE_BYTES (128*TSTRIDE)    // 18432
#define HG_SMEM (6*TILE_BYTES)      // 110592: A x3 stages, B x3 stages

// ================= bf16 HMMA GEMM (K-chunk 64, 3-stage cp.async, ldmatrix) =========
// C[M,512] = Acat[M,Ktot] @ W[Ktot,512] + bias, then optional ⊙ scale[row/196, col]
__global__ void __launch_bounds__(256, 2) hgemm_kernel(
    const __nv_bfloat16* __restrict__ A1,
    const __nv_bfloat16* __restrict__ A2,
    const __nv_bfloat16* __restrict__ Bt,
    const float* __restrict__ bias,
    const float* __restrict__ scale,
    void* __restrict__ Cout, int c_is_bf16,
    int K1, int Ktot)
{
    extern __shared__ char sm[];
    const uint32_t sa_base = smem_u32(sm);
    const uint32_t sb_base = sa_base + 3 * TILE_BYTES;

    const int tid  = threadIdx.x;
    const int m0   = blockIdx.y * 128;
    const int n0   = blockIdx.x * 128;
    const int warp = tid >> 5;
    const int lane = tid & 31;
    const int wm = warp >> 2;
    const int wn = warp & 3;
    const int g  = lane >> 2;
    const int t  = lane & 3;

    float acc[4][4][4];
    #pragma unroll
    for (int i = 0; i < 4; i++)
        #pragma unroll
        for (int j = 0; j < 4; j++)
            #pragma unroll
            for (int k = 0; k < 4; k++) acc[i][j][k] = 0.f;

    const int nch = Ktot >> 6;

    auto load_tile = [&](int c) {
        const int kt = c << 6;
        const int s = c % 3;
        uint32_t ab = sa_base + s * TILE_BYTES;
        uint32_t bb = sb_base + s * TILE_BYTES;
        #pragma unroll
        for (int i = 0; i < 4; i++) {
            int chunk = tid + (i << 8);
            int row = chunk >> 3, cc = chunk & 7;
            int kg = kt + (cc << 3);
            const __nv_bfloat16* sa = (kg < K1)
                ? (A1 + (size_t)(m0 + row) * K1 + kg)
                : (A2 + (size_t)(m0 + row) * Dz + (kg - K1));
            cp16(ab + row * TSTRIDE + cc * 16, sa);
            cp16(bb + row * TSTRIDE + cc * 16,
                 Bt + (size_t)(n0 + row) * Ktot + kt + (cc << 3));
        }
        asm volatile("cp.async.commit_group;" ::: "memory");
    };

    load_tile(0);
    load_tile(1);
    for (int c = 0; c < nch; c++) {
        if (c + 1 < nch) asm volatile("cp.async.wait_group 1;" ::: "memory");
        else             asm volatile("cp.async.wait_group 0;" ::: "memory");
        __syncthreads();
        if (c + 2 < nch) load_tile(c + 2);

        const int s = c % 3;
        const uint32_t ab = sa_base + s * TILE_BYTES;
        const uint32_t bb = sb_base + s * TILE_BYTES;
        #pragma unroll
        for (int ks = 0; ks < 4; ks++) {
            uint32_t bfr[4][2];
            #pragma unroll
            for (int j = 0; j < 2; j++) {
                uint32_t addr = bb + (uint32_t)((wn * 32 + j * 16 + ((lane >> 4) & 1) * 8
                                + (lane & 7)) * TSTRIDE + ks * 32 + ((lane >> 3) & 1) * 16);
                ldm4(bfr[2*j][0], bfr[2*j][1], bfr[2*j+1][0], bfr[2*j+1][1], addr);
            }
            #pragma unroll
            for (int am = 0; am < 4; am++) {
                uint32_t addr = ab + (uint32_t)((wm * 64 + am * 16 + (lane & 15)) * TSTRIDE
                                + ks * 32 + ((lane >> 4) & 1) * 16);
                uint32_t a0, a1, a2, a3;
                ldm4(a0, a1, a2, a3, addr);
                #pragma unroll
                for (int an = 0; an < 4; an++)
                    mma_bf16(acc[am][an], a0, a1, a2, a3, bfr[an][0], bfr[an][1]);
            }
        }
    }

    #pragma unroll
    for (int am = 0; am < 4; am++) {
        int r0 = m0 + wm * 64 + am * 16 + g;
        int r1 = r0 + 8;
        #pragma unroll
        for (int an = 0; an < 4; an++) {
            int col = n0 + wn * 32 + an * 8 + t * 2;
            float b0 = bias[col], b1 = bias[col + 1];
            float v00 = acc[am][an][0] + b0, v01 = acc[am][an][1] + b1;
            float v10 = acc[am][an][2] + b0, v11 = acc[am][an][3] + b1;
            if (scale) {
                const float* s0 = scale + (size_t)(r0 / HWz) * Dz + col;
                const float* s1 = scale + (size_t)(r1 / HWz) * Dz + col;
                v00 *= s0[0]; v01 *= s0[1];
                v10 *= s1[0]; v11 *= s1[1];
            }
            if (c_is_bf16) {
                union { __nv_bfloat162 h; uint32_t u; } p0, p1;
                p0.h = __floats2bfloat162_rn(v00, v01);
                p1.h = __floats2bfloat162_rn(v10, v11);
                *(uint32_t*)((__nv_bfloat16*)Cout + (size_t)r0 * Dz + col) = p0.u;
                *(uint32_t*)((__nv_bfloat16*)Cout + (size_t)r1 * Dz + col) = p1.u;
            } else {
                *(float2*)((float*)Cout + (size_t)r0 * Dz + col) = make_float2(v00, v01);
                *(float2*)((float*)Cout + (size_t)r1 * Dz + col) = make_float2(v10, v11);
            }
        }
    }
}

// ---------------- fp32 -> bf16 bulk convert ----------------
__global__ void __launch_bounds__(256) f2bf_kernel(const float* __restrict__ in,
                                                   __nv_bfloat16* __restrict__ out)
{
    size_t i = ((size_t)blockIdx.x * 256 + threadIdx.x) * 4;
    float4 v = *(const float4*)(in + i);
    union { __nv_bfloat162 h; uint32_t u; } p0, p1;
    p0.h = __floats2bfloat162_rn(v.x, v.y);
    p1.h = __floats2bfloat162_rn(v.z, v.w);
    *(uint2*)(out + i) = make_uint2(p0.u, p1.u);
}

// ---------------- weight transpose: Wt[n][k] = (bf16) W[k][n] ----------------
__global__ void __launch_bounds__(256) transpose_w_kernel(
    const float* __restrict__ W, __nv_bfloat16* __restrict__ Wt, int K, int N)
{
    __shared__ float t[32][33];
    int k0 = blockIdx.x * 32, n0 = blockIdx.y * 32;
    int x = threadIdx.x & 31, y = threadIdx.x >> 5;
    #pragma unroll
    for (int j = 0; j < 32; j += 8)
        t[y + j][x] = W[(size_t)(k0 + y + j) * N + n0 + x];
    __syncthreads();
    #pragma unroll
    for (int j = 0; j < 32; j += 8)
        Wt[(size_t)(n0 + y + j) * K + k0 + x] = __float2bfloat16(t[x][y + j]);
}

// ---------------- fp32 SGEMM, split-K (gridDim.z), concat-A / stacked-B ----------
// C must be pre-zeroed. Each z-split accumulates its K-range via atomicAdd.
// bias (+bias2) added by split z==0.
__global__ void __launch_bounds__(256) sgemm_kernel(
    const float* __restrict__ A1, const float* __restrict__ A2,
    const float* __restrict__ B1, const float* __restrict__ B2,
    const float* __restrict__ bias, const float* __restrict__ bias2,
    float* __restrict__ C,
    int M, int N, int K1, int KB1, int Ktot)
{
    __shared__ float As[8][128];
    __shared__ float Bs[8][128];
    const int tid = threadIdx.x;
    const int m0 = blockIdx.y * 128;
    const int n0 = blockIdx.x * 128;
    const int Kc = Ktot / gridDim.z;
    const int kbeg = blockIdx.z * Kc;
    const int tx = tid & 15;
    const int ty = tid >> 4;
    const int aRow = tid >> 1;
    const int aCol = (tid & 1) << 2;
    const int bRow = tid >> 5;
    const int bCol = (tid & 31) << 2;

    float acc[8][8];
    #pragma unroll
    for (int i = 0; i < 8; i++)
        #pragma unroll
        for (int j = 0; j < 8; j++) acc[i][j] = 0.f;

    for (int kt = kbeg; kt < kbeg + Kc; kt += 8) {
        int kg = kt + aCol;
        const float* ap = (kg < K1)
            ? (A1 + (size_t)(m0 + aRow) * K1 + kg)
            : (A2 + (size_t)(m0 + aRow) * Dz + (kg - K1));
        float4 a = *(const float4*)ap;
        As[aCol + 0][aRow] = a.x;
        As[aCol + 1][aRow] = a.y;
        As[aCol + 2][aRow] = a.z;
        As[aCol + 3][aRow] = a.w;
        int kr = kt + bRow;
        const float* bp = (kr < KB1)
            ? (B1 + (size_t)kr * N + n0 + bCol)
            : (B2 + (size_t)(kr - KB1) * N + n0 + bCol);
        *(float4*)&Bs[bRow][bCol] = *(const float4*)bp;
        __syncthreads();
        #pragma unroll
        for (int k = 0; k < 8; k++) {
            float ar[8], br[8];
            #pragma unroll
            for (int i = 0; i < 8; i++) ar[i] = As[k][ty * 8 + i];
            #pragma unroll
            for (int j = 0; j < 8; j++) br[j] = Bs[k][tx * 8 + j];
            #pragma unroll
            for (int i = 0; i < 8; i++)
                #pragma unroll
                for (int j = 0; j < 8; j++)
                    acc[i][j] = fmaf(ar[i], br[j], acc[i][j]);
        }
        __syncthreads();
    }
    #pragma unroll
    for (int i = 0; i < 8; i++) {
        int row = m0 + ty * 8 + i;
        float* crow = C + (size_t)row * N + n0 + tx * 8;
        #pragma unroll
        for (int j = 0; j < 8; j++) {
            float v = acc[i][j];
            if (blockIdx.z == 0) {
                v += bias[n0 + tx * 8 + j];
                if (bias2) v += bias2[n0 + tx * 8 + j];
            }
            if (gridDim.z == 1) crow[j] = v;
            else atomicAdd(&crow[j], v);
        }
    }
}

// ---------------- cai[b,s] = sum_d cqi[b,d]*cws[b,s,d]*W_cai[d] ----------------
__global__ void __launch_bounds__(256) cai_kernel(const float* __restrict__ cws,
                                                  const float* __restrict__ Wcai)
{
    int warp = (blockIdx.x * blockDim.x + threadIdx.x) >> 5;
    int lane = threadIdx.x & 31;
    if (warp >= Bz * Sz) return;
    int b = warp / Sz;
    const float* cq = g_cqi + b * Dz;
    const float* cw = cws + (size_t)warp * Dz;
    float sum = 0.f;
    #pragma unroll 4
    for (int d = lane; d < Dz; d += 32)
        sum += cq[d] * cw[d] * Wcai[d];
    #pragma unroll
    for (int o = 16; o; o >>= 1) sum += __shfl_xor_sync(0xffffffffu, sum, o);
    if (lane == 0) g_cai[warp] = sum;
}

// ---------------- softmax over S + ci reduction ----------------
__global__ void __launch_bounds__(128) ci_kernel(const float* __restrict__ cws)
{
    int b = blockIdx.x, tid = threadIdx.x;
    __shared__ float wsm[Sz];
    __shared__ float red[4];
    float x = g_cai[b * Sz + tid];
    float m = x;
    #pragma unroll
    for (int o = 16; o; o >>= 1) m = fmaxf(m, __shfl_xor_sync(0xffffffffu, m, o));
    if ((tid & 31) == 0) red[tid >> 5] = m;
    __syncthreads();
    float bm = fmaxf(fmaxf(red[0], red[1]), fmaxf(red[2], red[3]));
    __syncthreads();
    float e = fexp(x - bm);
    float s = e;
    #pragma unroll
    for (int o = 16; o; o >>= 1) s += __shfl_xor_sync(0xffffffffu, s, o);
    if ((tid & 31) == 0) red[tid >> 5] = s;
    __syncthreads();
    float bs = red[0] + red[1] + red[2] + red[3];
    wsm[tid] = e / bs;
    __syncthreads();
    for (int d = tid; d < Dz; d += 128) {
        float acc = 0.f;
        #pragma unroll 8
        for (int s2 = 0; s2 < Sz; s2++)
            acc += wsm[s2] * cws[((size_t)b * Sz + s2) * Dz + d];
        g_ci[b * Dz + d] = acc;
    }
}

// ---------------- double softmax + ri, smem-staged, bf16 rai input ----------------
#define RS_SMEM (HWz*128*4)   // 196*128 fp32 = 100352 B
__global__ void __launch_bounds__(128) rsoft_kernel(const __nv_bfloat16* __restrict__ rai,
                                                    const float* __restrict__ Kt)
{
    extern __shared__ float sd[];   // [196][128]
    const int b = blockIdx.x;
    const int d0 = blockIdx.y * 128;
    const int tid = threadIdx.x;
    const __nv_bfloat16* src = rai + (size_t)b * HWz * Dz + d0;

    // stage bf16 slab -> fp32 smem
    for (int i = tid; i < HWz * 32; i += 128) {
        int pos = i >> 5, c4 = (i & 31) << 2;
        uint2 raw = *(const uint2*)(src + (size_t)pos * Dz + c4);
        float2 f01 = __bfloat1622float2(((const __nv_bfloat162*)&raw)[0]);
        float2 f23 = __bfloat1622float2(((const __nv_bfloat162*)&raw)[1]);
        float* dst = sd + pos * 128 + c4;
        dst[0] = f01.x; dst[1] = f01.y; dst[2] = f23.x; dst[3] = f23.y;
    }
    __syncthreads();

    for (int w = 0; w < Wz; w++) {
        float v[Hz];
        float mx = -1e30f;
        #pragma unroll
        for (int h = 0; h < Hz; h++) { v[h] = sd[(h * Wz + w) * 128 + tid]; mx = fmaxf(mx, v[h]); }
        float s = 0.f;
        #pragma unroll
        for (int h = 0; h < Hz; h++) { v[h] = fexp(v[h] - mx); s += v[h]; }
        float inv = 1.f / s;
        #pragma unroll
        for (int h = 0; h < Hz; h++) sd[(h * Wz + w) * 128 + tid] = v[h] * inv;
    }
    __syncthreads();

    const float* kp = Kt + (size_t)b * HWz * Dz + d0 + tid;
    float acc = 0.f;
    for (int h = 0; h < Hz; h++) {
        float v[Wz];
        float mx = -1e30f;
        #pragma unroll
        for (int w = 0; w < Wz; w++) { v[w] = sd[(h * Wz + w) * 128 + tid]; mx = fmaxf(mx, v[w]); }
        float s = 0.f;
        #pragma unroll
        for (int w = 0; w < Wz; w++) { v[w] = fexp(v[w] - mx); s += v[w]; }
        float inv = 1.f / s;
        #pragma unroll
        for (int w = 0; w < Wz; w++) acc += v[w] * inv * kp[(size_t)(h * Wz + w) * Dz];
    }
    g_ri[b * Dz + d0 + tid] = acc;
}

// ---------------- write attention ----------------
__global__ void __launch_bounds__(512) sa_kernel(const float* __restrict__ C_past,
                                                 const float* __restrict__ M_past,
                                                 const float* __restrict__ Wwcc)
{
    int b = blockIdx.x, tid = threadIdx.x;
    int lane = tid & 31, warp = tid >> 5;
    __shared__ float z[16];
    __shared__ float wsm[Tz];
    if (warp < Tz) {
        const float* cp = C_past + ((size_t)b * Tz + warp) * Dz;
        const float* cb = g_ci + b * Dz;
        float sum = 0.f;
        #pragma unroll 4
        for (int d = lane; d < Dz; d += 32) sum += cb[d] * cp[d] * Wwcc[d];
        #pragma unroll
        for (int o = 16; o; o >>= 1) sum += __shfl_xor_sync(0xffffffffu, sum, o);
        if (lane == 0) z[warp] = sum;
    }
    __syncthreads();
    if (tid == 0) {
        float mx = -1e30f;
        for (int t = 0; t < Tz; t++) mx = fmaxf(mx, z[t]);
        float s = 0.f;
        for (int t = 0; t < Tz; t++) { float e = fexp(z[t] - mx); wsm[t] = e; s += e; }
        float inv = 1.f / s;
        for (int t = 0; t < Tz; t++) wsm[t] *= inv;
    }
    __syncthreads();
    float acc = 0.f;
    #pragma unroll
    for (int t = 0; t < Tz; t++)
        acc += wsm[t] * M_past[((size_t)b * Tz + t) * Dz + tid];
    g_mi_sa[b * Dz + tid] = acc;
}

// ---------------- gate + final ----------------
__global__ void __launch_bounds__(512) final_kernel(const float* __restrict__ mi_1,
                                                    const float* __restrict__ Wwci,
                                                    const float* __restrict__ bwci,
                                                    float* __restrict__ out)
{
    int b = blockIdx.x, tid = threadIdx.x;
    __shared__ float red[16];
    __shared__ float gsh;
    float civ = g_ci[b * Dz + tid];
    float sum = civ * Wwci[tid];
    #pragma unroll
    for (int o = 16; o; o >>= 1) sum += __shfl_xor_sync(0xffffffffu, sum, o);
    if ((tid & 31) == 0) red[tid >> 5] = sum;
    __syncthreads();
    if (tid < 32) {
        float v = (tid < 16) ? red[tid] : 0.f;
        #pragma unroll
        for (int o = 8; o; o >>= 1) v += __shfl_xor_sync(0xffffffffu, v, o);
        if (tid == 0) gsh = 1.f / (1.f + expf(-(v + bwci[0])));
    }
    __syncthreads();
    float g = gsh;
    float mi = g * mi_1[b * Dz + tid] + (1.f - g) * g_mi_prime[b * Dz + tid];
    out[b * Dz + tid] = civ;
    out[(size_t)Bz * Dz + b * Dz + tid] = mi;
}

// ---------------- launch ----------------
extern "C" void kernel_launch(void* const* d_in, const int* in_sizes, int n_in,
                              void* d_out, int out_size)
{
    const float* ci_1   = (const float*)d_in[0];
    const float* mi_1   = (const float*)d_in[1];
    const float* q      = (const float*)d_in[2];
    const float* cws    = (const float*)d_in[3];
    const float* Kt     = (const float*)d_in[4];
    const float* C_past = (const float*)d_in[5];
    const float* M_past = (const float*)d_in[6];
    const float* W_cq   = (const float*)d_in[7];
    const float* b_cq   = (const float*)d_in[8];
    const float* W_cqi  = (const float*)d_in[9];
    const float* b_cqi  = (const float*)d_in[10];
    const float* W_cai  = (const float*)d_in[11];
    const float* W_rm   = (const float*)d_in[13];
    const float* b_rm   = (const float*)d_in[14];
    const float* W_rk   = (const float*)d_in[15];
    const float* b_rk   = (const float*)d_in[16];
    const float* W_rik  = (const float*)d_in[17];
    const float* b_rik  = (const float*)d_in[18];
    const float* W_rci  = (const float*)d_in[19];
    const float* b_rci  = (const float*)d_in[20];
    const float* W_wrm  = (const float*)d_in[21];
    const float* b_wrm  = (const float*)d_in[22];
    const float* W_wcc  = (const float*)d_in[23];
    const float* W_wsa  = (const float*)d_in[25];
    const float* b_wsa  = (const float*)d_in[26];
    const float* W_winfo= (const float*)d_in[27];
    const float* b_winfo= (const float*)d_in[28];
    const float* W_wci  = (const float*)d_in[29];
    const float* b_wci  = (const float*)d_in[30];
    float* out = (float*)d_out;

    float *qi, *cqi, *ci, *rm, *ri, *mi_info, *mi_sa, *mi_prime;
    __nv_bfloat16 *rai_bf, *K_bf, *rk_bf, *ip_bf, *Wt_rk, *Wt_rik, *Wt_rci;
    cudaGetSymbolAddress((void**)&qi, g_qi);
    cudaGetSymbolAddress((void**)&cqi, g_cqi);
    cudaGetSymbolAddress((void**)&ci, g_ci);
    cudaGetSymbolAddress((void**)&rm, g_rm);
    cudaGetSymbolAddress((void**)&rai_bf, g_rai_bf);
    cudaGetSymbolAddress((void**)&ri, g_ri);
    cudaGetSymbolAddress((void**)&mi_info, g_mi_info);
    cudaGetSymbolAddress((void**)&mi_sa, g_mi_sa);
    cudaGetSymbolAddress((void**)&mi_prime, g_mi_prime);
    cudaGetSymbolAddress((void**)&K_bf, g_K_bf);
    cudaGetSymbolAddress((void**)&rk_bf, g_rk_bf);
    cudaGetSymbolAddress((void**)&ip_bf, g_ip_bf);
    cudaGetSymbolAddress((void**)&Wt_rk, g_Wt_rk);
    cudaGetSymbolAddress((void**)&Wt_rik, g_Wt_rik);
    cudaGetSymbolAddress((void**)&Wt_rci, g_Wt_rci);

    cudaFuncSetAttribute(hgemm_kernel,
                         cudaFuncAttributeMaxDynamicSharedMemorySize, HG_SMEM);
    cudaFuncSetAttribute(rsoft_kernel,
                         cudaFuncAttributeMaxDynamicSharedMemorySize, RS_SMEM);

    const size_t SMALL = (size_t)Bz * Dz * sizeof(float);
    dim3 gsk(Dz / 128, Bz / 128, 4);   // small GEMMs, split-K 4: 32 CTAs
    dim3 gh(Dz / 128, Mbig / 128);     // big GEMMs: (4, 392)

    // ---- zero split-K accumulation targets (capturable) ----
    cudaMemsetAsync(qi, 0, SMALL);
    cudaMemsetAsync(cqi, 0, SMALL);
    cudaMemsetAsync(rm, 0, SMALL);
    cudaMemsetAsync(mi_info, 0, SMALL);
    cudaMemsetAsync(mi_prime, 0, SMALL);

    // ---- precompute ----
    f2bf_kernel<<<(Mbig * Dz) / 1024, 256>>>(Kt, K_bf);
    transpose_w_kernel<<<dim3(Dz/32, Dz/32), 256>>>(W_rk, Wt_rk, Dz, Dz);
    transpose_w_kernel<<<dim3(2*Dz/32, Dz/32), 256>>>(W_rik, Wt_rik, 2*Dz, Dz);
    transpose_w_kernel<<<dim3(Dz/32, Dz/32), 256>>>(W_rci, Wt_rci, Dz, Dz);
    sgemm_kernel<<<gsk, 256>>>(mi_1, nullptr, W_rm, nullptr, b_rm, nullptr, rm,
                               Bz, Dz, Dz, 2*Dz, Dz);

    // ---- GEMM1: rk_bf = rm ⊙ (K @ W_rk + b_rk) ----
    hgemm_kernel<<<gh, 256, HG_SMEM>>>(K_bf, nullptr, Wt_rk, b_rk, rm, rk_bf, 1, Dz, Dz);

    // ---- control (fp32, split-K) ----
    sgemm_kernel<<<gsk, 256>>>(q, nullptr, W_cq, nullptr, b_cq, nullptr, qi,
                               Bz, Dz, Dz, 2*Dz, Dz);
    sgemm_kernel<<<gsk, 256>>>(ci_1, qi, W_cqi, nullptr, b_cqi, nullptr, cqi,
                               Bz, Dz, Dz, 2*Dz, 2*Dz);
    cai_kernel<<<(Bz * Sz) / 8, 256>>>(cws, W_cai);
    ci_kernel<<<Bz, 128>>>(cws);

    // ---- read path ----
    hgemm_kernel<<<gh, 256, HG_SMEM>>>(rk_bf, K_bf, Wt_rik, b_rik, ci, ip_bf, 1, Dz, 2*Dz);
    // rai (bf16) = ip_bf @ W_rci + b_rci
    hgemm_kernel<<<gh, 256, HG_SMEM>>>(ip_bf, nullptr, Wt_rci, b_rci, nullptr, rai_bf, 1, Dz, Dz);
    rsoft_kernel<<<dim3(Bz, Dz/128), 128, RS_SMEM>>>(rai_bf, Kt);

    // ---- write (fp32, split-K) ----
    sgemm_kernel<<<gsk, 256>>>(ri, mi_1, W_wrm, nullptr, b_wrm, nullptr, mi_info,
                               Bz, Dz, Dz, 2*Dz, 2*Dz);
    sa_kernel<<<Bz, 512>>>(C_past, M_past, W_wcc);
    sgemm_kernel<<<gsk, 256>>>(mi_sa, mi_info, W_wsa, W_winfo, b_wsa, b_winfo, mi_prime,
                               Bz, Dz, Dz, Dz, 2*Dz);
    final_kernel<<<Bz, 512>>>(mi_1, W_wci, b_wci, out);
}

// round 17
// speedup vs baseline: 2.7229x; 1.1360x over previous
#include <cuda_runtime.h>
#include <cuda_bf16.h>
#include <stdint.h>
#include <math.h>

#define Bz 256
#define Sz 128
#define Hz 14
#define Wz 14
#define Tz 12
#define Dz 512
#define HWz (Hz*Wz)
#define Mbig (Bz*HWz)   // 50176

// ---------------- scratch (device globals; no allocation) ----------------
__device__ float g_qi[Bz*Dz];
__device__ float g_cqi[Bz*Dz];
__device__ float g_cai[Bz*Sz];
__device__ float g_ci[Bz*Dz];
__device__ float g_rm[Bz*Dz];
__device__ float g_ri[Bz*Dz];
__device__ float g_mi_info[Bz*Dz];
__device__ float g_mi_sa[Bz*Dz];
__device__ float g_mi_prime[Bz*Dz];
__device__ __nv_bfloat16 g_rai_bf[(size_t)Mbig*Dz];
__device__ __nv_bfloat16 g_K_bf[(size_t)Mbig*Dz];
__device__ __nv_bfloat16 g_rk_bf[(size_t)Mbig*Dz];   // rm ⊙ (K@W_rk + b_rk)
__device__ __nv_bfloat16 g_ip_bf[(size_t)Mbig*Dz];   // ci ⊙ (concat@W_rik + b_rik)
__device__ __nv_bfloat16 g_Wt_rk[Dz*Dz];
__device__ __nv_bfloat16 g_Wt_rik[2*Dz*Dz];
__device__ __nv_bfloat16 g_Wt_rci[Dz*Dz];

// ================= helpers =================
__device__ __forceinline__ uint32_t smem_u32(const void* p) {
    uint32_t a;
    asm("{ .reg .u64 t; cvta.to.shared.u64 t, %1; cvt.u32.u64 %0, t; }" : "=r"(a) : "l"(p));
    return a;
}
__device__ __forceinline__ void cp16(uint32_t dst, const void* src) {
    asm volatile("cp.async.cg.shared.global [%0], [%1], 16;" :: "r"(dst), "l"(src) : "memory");
}
__device__ __forceinline__ void mma_bf16(float* c, uint32_t a0, uint32_t a1,
                                         uint32_t a2, uint32_t a3,
                                         uint32_t b0, uint32_t b1) {
    asm volatile("mma.sync.aligned.m16n8k16.row.col.f32.bf16.bf16.f32 "
        "{%0,%1,%2,%3}, {%4,%5,%6,%7}, {%8,%9}, {%0,%1,%2,%3};"
        : "+f"(c[0]), "+f"(c[1]), "+f"(c[2]), "+f"(c[3])
        : "r"(a0), "r"(a1), "r"(a2), "r"(a3), "r"(b0), "r"(b1));
}
__device__ __forceinline__ void ldm4(uint32_t& r0, uint32_t& r1, uint32_t& r2,
                                     uint32_t& r3, uint32_t addr) {
    asm volatile("ldmatrix.sync.aligned.m8n8.x4.shared.b16 {%0,%1,%2,%3}, [%4];"
        : "=r"(r0), "=r"(r1), "=r"(r2), "=r"(r3) : "r"(addr));
}

// fast exp on the FMA pipe
__device__ __forceinline__ float fexp(float x) {
    float t = fmaxf(x * 1.44269504f, -126.0f);
    float n = floorf(t);
    float f = t - n;
    float p = 1.8775767e-3f;
    p = fmaf(p, f, 8.9893397e-3f);
    p = fmaf(p, f, 5.5826318e-2f);
    p = fmaf(p, f, 2.4015361e-1f);
    p = fmaf(p, f, 6.9315308e-1f);
    p = fmaf(p, f, 9.9999994e-1f);
    return __int_as_float(((int)n + 127) << 23) * p;
}

#define TSTRIDE 144                 // bytes per smem tile row (64 bf16 + 8 pad)
#define TILE_BYTES (128*TSTRIDE)    // 18432
#define HG_SMEM (6*TILE_BYTES)      // 110592: A x3 stages, B x3 stages

// ================= bf16 HMMA GEMM (K-chunk 64, 3-stage cp.async, ldmatrix) =========
// C[M,512] = Acat[M,Ktot] @ W[Ktot,512] + bias, then optional ⊙ scale[row/196, col]
__global__ void __launch_bounds__(256, 2) hgemm_kernel(
    const __nv_bfloat16* __restrict__ A1,
    const __nv_bfloat16* __restrict__ A2,
    const __nv_bfloat16* __restrict__ Bt,
    const float* __restrict__ bias,
    const float* __restrict__ scale,
    void* __restrict__ Cout, int c_is_bf16,
    int K1, int Ktot)
{
    extern __shared__ char sm[];
    const uint32_t sa_base = smem_u32(sm);
    const uint32_t sb_base = sa_base + 3 * TILE_BYTES;

    const int tid  = threadIdx.x;
    const int m0   = blockIdx.y * 128;
    const int n0   = blockIdx.x * 128;
    const int warp = tid >> 5;
    const int lane = tid & 31;
    const int wm = warp >> 2;
    const int wn = warp & 3;
    const int g  = lane >> 2;
    const int t  = lane & 3;

    float acc[4][4][4];
    #pragma unroll
    for (int i = 0; i < 4; i++)
        #pragma unroll
        for (int j = 0; j < 4; j++)
            #pragma unroll
            for (int k = 0; k < 4; k++) acc[i][j][k] = 0.f;

    const int nch = Ktot >> 6;

    auto load_tile = [&](int c) {
        const int kt = c << 6;
        const int s = c % 3;
        uint32_t ab = sa_base + s * TILE_BYTES;
        uint32_t bb = sb_base + s * TILE_BYTES;
        #pragma unroll
        for (int i = 0; i < 4; i++) {
            int chunk = tid + (i << 8);
            int row = chunk >> 3, cc = chunk & 7;
            int kg = kt + (cc << 3);
            const __nv_bfloat16* sa = (kg < K1)
                ? (A1 + (size_t)(m0 + row) * K1 + kg)
                : (A2 + (size_t)(m0 + row) * Dz + (kg - K1));
            cp16(ab + row * TSTRIDE + cc * 16, sa);
            cp16(bb + row * TSTRIDE + cc * 16,
                 Bt + (size_t)(n0 + row) * Ktot + kt + (cc << 3));
        }
        asm volatile("cp.async.commit_group;" ::: "memory");
    };

    load_tile(0);
    load_tile(1);
    for (int c = 0; c < nch; c++) {
        if (c + 1 < nch) asm volatile("cp.async.wait_group 1;" ::: "memory");
        else             asm volatile("cp.async.wait_group 0;" ::: "memory");
        __syncthreads();
        if (c + 2 < nch) load_tile(c + 2);

        const int s = c % 3;
        const uint32_t ab = sa_base + s * TILE_BYTES;
        const uint32_t bb = sb_base + s * TILE_BYTES;
        #pragma unroll
        for (int ks = 0; ks < 4; ks++) {
            uint32_t bfr[4][2];
            #pragma unroll
            for (int j = 0; j < 2; j++) {
                uint32_t addr = bb + (uint32_t)((wn * 32 + j * 16 + ((lane >> 4) & 1) * 8
                                + (lane & 7)) * TSTRIDE + ks * 32 + ((lane >> 3) & 1) * 16);
                ldm4(bfr[2*j][0], bfr[2*j][1], bfr[2*j+1][0], bfr[2*j+1][1], addr);
            }
            #pragma unroll
            for (int am = 0; am < 4; am++) {
                uint32_t addr = ab + (uint32_t)((wm * 64 + am * 16 + (lane & 15)) * TSTRIDE
                                + ks * 32 + ((lane >> 4) & 1) * 16);
                uint32_t a0, a1, a2, a3;
                ldm4(a0, a1, a2, a3, addr);
                #pragma unroll
                for (int an = 0; an < 4; an++)
                    mma_bf16(acc[am][an], a0, a1, a2, a3, bfr[an][0], bfr[an][1]);
            }
        }
    }

    #pragma unroll
    for (int am = 0; am < 4; am++) {
        int r0 = m0 + wm * 64 + am * 16 + g;
        int r1 = r0 + 8;
        #pragma unroll
        for (int an = 0; an < 4; an++) {
            int col = n0 + wn * 32 + an * 8 + t * 2;
            float b0 = bias[col], b1 = bias[col + 1];
            float v00 = acc[am][an][0] + b0, v01 = acc[am][an][1] + b1;
            float v10 = acc[am][an][2] + b0, v11 = acc[am][an][3] + b1;
            if (scale) {
                const float* s0 = scale + (size_t)(r0 / HWz) * Dz + col;
                const float* s1 = scale + (size_t)(r1 / HWz) * Dz + col;
                v00 *= s0[0]; v01 *= s0[1];
                v10 *= s1[0]; v11 *= s1[1];
            }
            if (c_is_bf16) {
                union { __nv_bfloat162 h; uint32_t u; } p0, p1;
                p0.h = __floats2bfloat162_rn(v00, v01);
                p1.h = __floats2bfloat162_rn(v10, v11);
                *(uint32_t*)((__nv_bfloat16*)Cout + (size_t)r0 * Dz + col) = p0.u;
                *(uint32_t*)((__nv_bfloat16*)Cout + (size_t)r1 * Dz + col) = p1.u;
            } else {
                *(float2*)((float*)Cout + (size_t)r0 * Dz + col) = make_float2(v00, v01);
                *(float2*)((float*)Cout + (size_t)r1 * Dz + col) = make_float2(v10, v11);
            }
        }
    }
}

// ---------------- fp32 -> bf16 bulk convert ----------------
__global__ void __launch_bounds__(256) f2bf_kernel(const float* __restrict__ in,
                                                   __nv_bfloat16* __restrict__ out)
{
    size_t i = ((size_t)blockIdx.x * 256 + threadIdx.x) * 4;
    float4 v = *(const float4*)(in + i);
    union { __nv_bfloat162 h; uint32_t u; } p0, p1;
    p0.h = __floats2bfloat162_rn(v.x, v.y);
    p1.h = __floats2bfloat162_rn(v.z, v.w);
    *(uint2*)(out + i) = make_uint2(p0.u, p1.u);
}

// ---------------- weight transpose: Wt[n][k] = (bf16) W[k][n] ----------------
__global__ void __launch_bounds__(256) transpose_w_kernel(
    const float* __restrict__ W, __nv_bfloat16* __restrict__ Wt, int K, int N)
{
    __shared__ float t[32][33];
    int k0 = blockIdx.x * 32, n0 = blockIdx.y * 32;
    int x = threadIdx.x & 31, y = threadIdx.x >> 5;
    #pragma unroll
    for (int j = 0; j < 32; j += 8)
        t[y + j][x] = W[(size_t)(k0 + y + j) * N + n0 + x];
    __syncthreads();
    #pragma unroll
    for (int j = 0; j < 32; j += 8)
        Wt[(size_t)(n0 + y + j) * K + k0 + x] = __float2bfloat16(t[x][y + j]);
}

// ---------------- fp32 SGEMM, split-K (gridDim.z), concat-A / stacked-B ----------
__global__ void __launch_bounds__(256) sgemm_kernel(
    const float* __restrict__ A1, const float* __restrict__ A2,
    const float* __restrict__ B1, const float* __restrict__ B2,
    const float* __restrict__ bias, const float* __restrict__ bias2,
    float* __restrict__ C,
    int M, int N, int K1, int KB1, int Ktot)
{
    __shared__ float As[8][128];
    __shared__ float Bs[8][128];
    const int tid = threadIdx.x;
    const int m0 = blockIdx.y * 128;
    const int n0 = blockIdx.x * 128;
    const int Kc = Ktot / gridDim.z;
    const int kbeg = blockIdx.z * Kc;
    const int tx = tid & 15;
    const int ty = tid >> 4;
    const int aRow = tid >> 1;
    const int aCol = (tid & 1) << 2;
    const int bRow = tid >> 5;
    const int bCol = (tid & 31) << 2;

    float acc[8][8];
    #pragma unroll
    for (int i = 0; i < 8; i++)
        #pragma unroll
        for (int j = 0; j < 8; j++) acc[i][j] = 0.f;

    for (int kt = kbeg; kt < kbeg + Kc; kt += 8) {
        int kg = kt + aCol;
        const float* ap = (kg < K1)
            ? (A1 + (size_t)(m0 + aRow) * K1 + kg)
            : (A2 + (size_t)(m0 + aRow) * Dz + (kg - K1));
        float4 a = *(const float4*)ap;
        As[aCol + 0][aRow] = a.x;
        As[aCol + 1][aRow] = a.y;
        As[aCol + 2][aRow] = a.z;
        As[aCol + 3][aRow] = a.w;
        int kr = kt + bRow;
        const float* bp = (kr < KB1)
            ? (B1 + (size_t)kr * N + n0 + bCol)
            : (B2 + (size_t)(kr - KB1) * N + n0 + bCol);
        *(float4*)&Bs[bRow][bCol] = *(const float4*)bp;
        __syncthreads();
        #pragma unroll
        for (int k = 0; k < 8; k++) {
            float ar[8], br[8];
            #pragma unroll
            for (int i = 0; i < 8; i++) ar[i] = As[k][ty * 8 + i];
            #pragma unroll
            for (int j = 0; j < 8; j++) br[j] = Bs[k][tx * 8 + j];
            #pragma unroll
            for (int i = 0; i < 8; i++)
                #pragma unroll
                for (int j = 0; j < 8; j++)
                    acc[i][j] = fmaf(ar[i], br[j], acc[i][j]);
        }
        __syncthreads();
    }
    #pragma unroll
    for (int i = 0; i < 8; i++) {
        int row = m0 + ty * 8 + i;
        float* crow = C + (size_t)row * N + n0 + tx * 8;
        #pragma unroll
        for (int j = 0; j < 8; j++) {
            float v = acc[i][j];
            if (blockIdx.z == 0) {
                v += bias[n0 + tx * 8 + j];
                if (bias2) v += bias2[n0 + tx * 8 + j];
            }
            if (gridDim.z == 1) crow[j] = v;
            else atomicAdd(&crow[j], v);
        }
    }
}

// ---------------- cai[b,s] = sum_d cqi[b,d]*cws[b,s,d]*W_cai[d] ----------------
__global__ void __launch_bounds__(256) cai_kernel(const float* __restrict__ cws,
                                                  const float* __restrict__ Wcai)
{
    int warp = (blockIdx.x * blockDim.x + threadIdx.x) >> 5;
    int lane = threadIdx.x & 31;
    if (warp >= Bz * Sz) return;
    int b = warp / Sz;
    const float* cq = g_cqi + b * Dz;
    const float* cw = cws + (size_t)warp * Dz;
    float sum = 0.f;
    #pragma unroll 4
    for (int d = lane; d < Dz; d += 32)
        sum += cq[d] * cw[d] * Wcai[d];
    #pragma unroll
    for (int o = 16; o; o >>= 1) sum += __shfl_xor_sync(0xffffffffu, sum, o);
    if (lane == 0) g_cai[warp] = sum;
}

// ---------------- softmax over S + ci reduction ----------------
__global__ void __launch_bounds__(128) ci_kernel(const float* __restrict__ cws)
{
    int b = blockIdx.x, tid = threadIdx.x;
    __shared__ float wsm[Sz];
    __shared__ float red[4];
    float x = g_cai[b * Sz + tid];
    float m = x;
    #pragma unroll
    for (int o = 16; o; o >>= 1) m = fmaxf(m, __shfl_xor_sync(0xffffffffu, m, o));
    if ((tid & 31) == 0) red[tid >> 5] = m;
    __syncthreads();
    float bm = fmaxf(fmaxf(red[0], red[1]), fmaxf(red[2], red[3]));
    __syncthreads();
    float e = fexp(x - bm);
    float s = e;
    #pragma unroll
    for (int o = 16; o; o >>= 1) s += __shfl_xor_sync(0xffffffffu, s, o);
    if ((tid & 31) == 0) red[tid >> 5] = s;
    __syncthreads();
    float bs = red[0] + red[1] + red[2] + red[3];
    wsm[tid] = e / bs;
    __syncthreads();
    for (int d = tid; d < Dz; d += 128) {
        float acc = 0.f;
        #pragma unroll 8
        for (int s2 = 0; s2 < Sz; s2++)
            acc += wsm[s2] * cws[((size_t)b * Sz + s2) * Dz + d];
        g_ci[b * Dz + d] = acc;
    }
}

// ---------------- double softmax + ri, smem-staged, bf16 rai input ----------------
#define RS_SMEM (HWz*128*4)   // 196*128 fp32 = 100352 B
__global__ void __launch_bounds__(128) rsoft_kernel(const __nv_bfloat16* __restrict__ rai,
                                                    const float* __restrict__ Kt)
{
    extern __shared__ float sd[];   // [196][128]
    const int b = blockIdx.x;
    const int d0 = blockIdx.y * 128;
    const int tid = threadIdx.x;
    const __nv_bfloat16* src = rai + (size_t)b * HWz * Dz + d0;

    for (int i = tid; i < HWz * 32; i += 128) {
        int pos = i >> 5, c4 = (i & 31) << 2;
        uint2 raw = *(const uint2*)(src + (size_t)pos * Dz + c4);
        float2 f01 = __bfloat1622float2(((const __nv_bfloat162*)&raw)[0]);
        float2 f23 = __bfloat1622float2(((const __nv_bfloat162*)&raw)[1]);
        float* dst = sd + pos * 128 + c4;
        dst[0] = f01.x; dst[1] = f01.y; dst[2] = f23.x; dst[3] = f23.y;
    }
    __syncthreads();

    for (int w = 0; w < Wz; w++) {
        float v[Hz];
        float mx = -1e30f;
        #pragma unroll
        for (int h = 0; h < Hz; h++) { v[h] = sd[(h * Wz + w) * 128 + tid]; mx = fmaxf(mx, v[h]); }
        float s = 0.f;
        #pragma unroll
        for (int h = 0; h < Hz; h++) { v[h] = fexp(v[h] - mx); s += v[h]; }
        float inv = 1.f / s;
        #pragma unroll
        for (int h = 0; h < Hz; h++) sd[(h * Wz + w) * 128 + tid] = v[h] * inv;
    }
    __syncthreads();

    const float* kp = Kt + (size_t)b * HWz * Dz + d0 + tid;
    float acc = 0.f;
    for (int h = 0; h < Hz; h++) {
        float v[Wz];
        float mx = -1e30f;
        #pragma unroll
        for (int w = 0; w < Wz; w++) { v[w] = sd[(h * Wz + w) * 128 + tid]; mx = fmaxf(mx, v[w]); }
        float s = 0.f;
        #pragma unroll
        for (int w = 0; w < Wz; w++) { v[w] = fexp(v[w] - mx); s += v[w]; }
        float inv = 1.f / s;
        #pragma unroll
        for (int w = 0; w < Wz; w++) acc += v[w] * inv * kp[(size_t)(h * Wz + w) * Dz];
    }
    g_ri[b * Dz + d0 + tid] = acc;
}

// ---------------- write attention ----------------
__global__ void __launch_bounds__(512) sa_kernel(const float* __restrict__ C_past,
                                                 const float* __restrict__ M_past,
                                                 const float* __restrict__ Wwcc)
{
    int b = blockIdx.x, tid = threadIdx.x;
    int lane = tid & 31, warp = tid >> 5;
    __shared__ float z[16];
    __shared__ float wsm[Tz];
    if (warp < Tz) {
        const float* cp = C_past + ((size_t)b * Tz + warp) * Dz;
        const float* cb = g_ci + b * Dz;
        float sum = 0.f;
        #pragma unroll 4
        for (int d = lane; d < Dz; d += 32) sum += cb[d] * cp[d] * Wwcc[d];
        #pragma unroll
        for (int o = 16; o; o >>= 1) sum += __shfl_xor_sync(0xffffffffu, sum, o);
        if (lane == 0) z[warp] = sum;
    }
    __syncthreads();
    if (tid == 0) {
        float mx = -1e30f;
        for (int t = 0; t < Tz; t++) mx = fmaxf(mx, z[t]);
        float s = 0.f;
        for (int t = 0; t < Tz; t++) { float e = fexp(z[t] - mx); wsm[t] = e; s += e; }
        float inv = 1.f / s;
        for (int t = 0; t < Tz; t++) wsm[t] *= inv;
    }
    __syncthreads();
    float acc = 0.f;
    #pragma unroll
    for (int t = 0; t < Tz; t++)
        acc += wsm[t] * M_past[((size_t)b * Tz + t) * Dz + tid];
    g_mi_sa[b * Dz + tid] = acc;
}

// ---------------- gate + final ----------------
__global__ void __launch_bounds__(512) final_kernel(const float* __restrict__ mi_1,
                                                    const float* __restrict__ Wwci,
                                                    const float* __restrict__ bwci,
                                                    float* __restrict__ out)
{
    int b = blockIdx.x, tid = threadIdx.x;
    __shared__ float red[16];
    __shared__ float gsh;
    float civ = g_ci[b * Dz + tid];
    float sum = civ * Wwci[tid];
    #pragma unroll
    for (int o = 16; o; o >>= 1) sum += __shfl_xor_sync(0xffffffffu, sum, o);
    if ((tid & 31) == 0) red[tid >> 5] = sum;
    __syncthreads();
    if (tid < 32) {
        float v = (tid < 16) ? red[tid] : 0.f;
        #pragma unroll
        for (int o = 8; o; o >>= 1) v += __shfl_xor_sync(0xffffffffu, v, o);
        if (tid == 0) gsh = 1.f / (1.f + expf(-(v + bwci[0])));
    }
    __syncthreads();
    float g = gsh;
    float mi = g * mi_1[b * Dz + tid] + (1.f - g) * g_mi_prime[b * Dz + tid];
    out[b * Dz + tid] = civ;
    out[(size_t)Bz * Dz + b * Dz + tid] = mi;
}

// ---------------- launch (graph fork/join: side stream hides control path) -------
extern "C" void kernel_launch(void* const* d_in, const int* in_sizes, int n_in,
                              void* d_out, int out_size)
{
    const float* ci_1   = (const float*)d_in[0];
    const float* mi_1   = (const float*)d_in[1];
    const float* q      = (const float*)d_in[2];
    const float* cws    = (const float*)d_in[3];
    const float* Kt     = (const float*)d_in[4];
    const float* C_past = (const float*)d_in[5];
    const float* M_past = (const float*)d_in[6];
    const float* W_cq   = (const float*)d_in[7];
    const float* b_cq   = (const float*)d_in[8];
    const float* W_cqi  = (const float*)d_in[9];
    const float* b_cqi  = (const float*)d_in[10];
    const float* W_cai  = (const float*)d_in[11];
    const float* W_rm   = (const float*)d_in[13];
    const float* b_rm   = (const float*)d_in[14];
    const float* W_rk   = (const float*)d_in[15];
    const float* b_rk   = (const float*)d_in[16];
    const float* W_rik  = (const float*)d_in[17];
    const float* b_rik  = (const float*)d_in[18];
    const float* W_rci  = (const float*)d_in[19];
    const float* b_rci  = (const float*)d_in[20];
    const float* W_wrm  = (const float*)d_in[21];
    const float* b_wrm  = (const float*)d_in[22];
    const float* W_wcc  = (const float*)d_in[23];
    const float* W_wsa  = (const float*)d_in[25];
    const float* b_wsa  = (const float*)d_in[26];
    const float* W_winfo= (const float*)d_in[27];
    const float* b_winfo= (const float*)d_in[28];
    const float* W_wci  = (const float*)d_in[29];
    const float* b_wci  = (const float*)d_in[30];
    float* out = (float*)d_out;

    float *qi, *cqi, *ci, *rm, *ri, *mi_info, *mi_sa, *mi_prime;
    __nv_bfloat16 *rai_bf, *K_bf, *rk_bf, *ip_bf, *Wt_rk, *Wt_rik, *Wt_rci;
    cudaGetSymbolAddress((void**)&qi, g_qi);
    cudaGetSymbolAddress((void**)&cqi, g_cqi);
    cudaGetSymbolAddress((void**)&ci, g_ci);
    cudaGetSymbolAddress((void**)&rm, g_rm);
    cudaGetSymbolAddress((void**)&rai_bf, g_rai_bf);
    cudaGetSymbolAddress((void**)&ri, g_ri);
    cudaGetSymbolAddress((void**)&mi_info, g_mi_info);
    cudaGetSymbolAddress((void**)&mi_sa, g_mi_sa);
    cudaGetSymbolAddress((void**)&mi_prime, g_mi_prime);
    cudaGetSymbolAddress((void**)&K_bf, g_K_bf);
    cudaGetSymbolAddress((void**)&rk_bf, g_rk_bf);
    cudaGetSymbolAddress((void**)&ip_bf, g_ip_bf);
    cudaGetSymbolAddress((void**)&Wt_rk, g_Wt_rk);
    cudaGetSymbolAddress((void**)&Wt_rik, g_Wt_rik);
    cudaGetSymbolAddress((void**)&Wt_rci, g_Wt_rci);

    cudaFuncSetAttribute(hgemm_kernel,
                         cudaFuncAttributeMaxDynamicSharedMemorySize, HG_SMEM);
    cudaFuncSetAttribute(rsoft_kernel,
                         cudaFuncAttributeMaxDynamicSharedMemorySize, RS_SMEM);

    const size_t SMALL = (size_t)Bz * Dz * sizeof(float);
    dim3 gsk(Dz / 128, Bz / 128, 4);   // small GEMMs, split-K 4
    dim3 gh(Dz / 128, Mbig / 128);     // big GEMMs: (4, 392)

    // ---- fork a side stream (captured via event fork/join) ----
    cudaStream_t s2;
    cudaStreamCreateWithFlags(&s2, cudaStreamNonBlocking);
    cudaEvent_t e0, e1, e2;
    cudaEventCreateWithFlags(&e0, cudaEventDisableTiming);
    cudaEventCreateWithFlags(&e1, cudaEventDisableTiming);
    cudaEventCreateWithFlags(&e2, cudaEventDisableTiming);

    cudaEventRecord(e0, 0);
    cudaStreamWaitEvent(s2, e0, 0);

    // ===== side stream: control path + GEMM2/3 weight transposes + sa =====
    cudaMemsetAsync(qi, 0, SMALL, s2);
    cudaMemsetAsync(cqi, 0, SMALL, s2);
    transpose_w_kernel<<<dim3(2*Dz/32, Dz/32), 256, 0, s2>>>(W_rik, Wt_rik, 2*Dz, Dz);
    transpose_w_kernel<<<dim3(Dz/32, Dz/32), 256, 0, s2>>>(W_rci, Wt_rci, Dz, Dz);
    sgemm_kernel<<<gsk, 256, 0, s2>>>(q, nullptr, W_cq, nullptr, b_cq, nullptr, qi,
                                      Bz, Dz, Dz, 2*Dz, Dz);
    sgemm_kernel<<<gsk, 256, 0, s2>>>(ci_1, qi, W_cqi, nullptr, b_cqi, nullptr, cqi,
                                      Bz, Dz, Dz, 2*Dz, 2*Dz);
    cai_kernel<<<(Bz * Sz) / 8, 256, 0, s2>>>(cws, W_cai);
    ci_kernel<<<Bz, 128, 0, s2>>>(cws);
    cudaEventRecord(e1, s2);                    // ci + Wt_rik/Wt_rci ready
    sa_kernel<<<Bz, 512, 0, s2>>>(C_past, M_past, W_wcc);
    cudaEventRecord(e2, s2);                    // mi_sa ready

    // ===== main stream: GEMM chain =====
    cudaMemsetAsync(rm, 0, SMALL);
    cudaMemsetAsync(mi_info, 0, SMALL);
    cudaMemsetAsync(mi_prime, 0, SMALL);
    f2bf_kernel<<<(Mbig * Dz) / 1024, 256>>>(Kt, K_bf);
    transpose_w_kernel<<<dim3(Dz/32, Dz/32), 256>>>(W_rk, Wt_rk, Dz, Dz);
    sgemm_kernel<<<gsk, 256>>>(mi_1, nullptr, W_rm, nullptr, b_rm, nullptr, rm,
                               Bz, Dz, Dz, 2*Dz, Dz);
    // GEMM1: rk_bf = rm ⊙ (K @ W_rk + b_rk)   (overlaps side-stream control path)
    hgemm_kernel<<<gh, 256, HG_SMEM>>>(K_bf, nullptr, Wt_rk, b_rk, rm, rk_bf, 1, Dz, Dz);

    cudaStreamWaitEvent(0, e1, 0);              // join: need ci + Wt_rik
    // GEMM2: ip_bf = ci ⊙ (concat(rk_bf, K) @ W_rik + b_rik)
    hgemm_kernel<<<gh, 256, HG_SMEM>>>(rk_bf, K_bf, Wt_rik, b_rik, ci, ip_bf, 1, Dz, 2*Dz);
    // GEMM3: rai (bf16) = ip_bf @ W_rci + b_rci
    hgemm_kernel<<<gh, 256, HG_SMEM>>>(ip_bf, nullptr, Wt_rci, b_rci, nullptr, rai_bf, 1, Dz, Dz);
    rsoft_kernel<<<dim3(Bz, Dz/128), 128, RS_SMEM>>>(rai_bf, Kt);

    // write path
    sgemm_kernel<<<gsk, 256>>>(ri, mi_1, W_wrm, nullptr, b_wrm, nullptr, mi_info,
                               Bz, Dz, Dz, 2*Dz, 2*Dz);
    cudaStreamWaitEvent(0, e2, 0);              // join: need mi_sa
    sgemm_kernel<<<gsk, 256>>>(mi_sa, mi_info, W_wsa, W_winfo, b_wsa, b_winfo, mi_prime,
                               Bz, Dz, Dz, Dz, 2*Dz);
    final_kernel<<<Bz, 512>>>(mi_1, W_wci, b_wci, out);
}